// round 9
// baseline (speedup 1.0000x reference)
#include <cuda_runtime.h>
#include <cuda_fp16.h>
#include <math.h>
#include <stdint.h>

// ---------------- problem constants ----------------
#define NB 8
#define NL 2048
#define NLP1 2049
#define NH 512
#define NHEADS 8
#define HDIM 64
#define NLAYERS 4

#define MPAD 16512          // 129*128 row capacity (A padding for cp.async)
#define QS 1536             // fused qkv row stride

// ---------------- scratch (device globals; no allocation) ----------------
__device__ float g_nodes[(size_t)NB * NL * NH];            // 32 MB
__device__ __align__(16) __half g_qkv[(size_t)NB * NLP1 * QS];  // 50 MB (fp16)
__device__ float g_relay[NB * NH];
__device__ float g_attr [NB * NH];
__device__ float g_part [(size_t)NB * 32 * NH];
__device__ __align__(16) __half g_a16[(size_t)MPAD * NH];  // 16.9 MB (GEMM A operand)
__device__ __align__(16) __half g_b16[(size_t)(512 + NLAYERS * 2048) * NH]; // 8.9 MB

// =====================================================================
//  low-level helpers
// =====================================================================
__device__ __forceinline__ uint32_t smem_u32(const void* p) {
    uint32_t a;
    asm("{ .reg .u64 t; cvta.to.shared.u64 t, %1; cvt.u32.u64 %0, t; }"
        : "=r"(a) : "l"(p));
    return a;
}

#define CP_ASYNC16(dst, src) \
    asm volatile("cp.async.cg.shared.global [%0], [%1], 16;" \
        :: "r"(dst), "l"(src) : "memory")
#define CP_COMMIT() asm volatile("cp.async.commit_group;" ::: "memory")
#define CP_WAIT(n)  asm volatile("cp.async.wait_group %0;" :: "n"(n) : "memory")

__device__ __forceinline__ void ldsm4(uint32_t* r, uint32_t addr) {
    asm volatile("ldmatrix.sync.aligned.m8n8.x4.shared.b16 {%0,%1,%2,%3}, [%4];"
        : "=r"(r[0]), "=r"(r[1]), "=r"(r[2]), "=r"(r[3]) : "r"(addr));
}

__device__ __forceinline__ void mma16816f(float* c, const uint32_t* a, const uint32_t* b) {
    asm volatile("mma.sync.aligned.m16n8k16.row.col.f32.f16.f16.f32 "
        "{%0,%1,%2,%3}, {%4,%5,%6,%7}, {%8,%9}, {%0,%1,%2,%3};"
        : "+f"(c[0]), "+f"(c[1]), "+f"(c[2]), "+f"(c[3])
        : "r"(a[0]), "r"(a[1]), "r"(a[2]), "r"(a[3]), "r"(b[0]), "r"(b[1]));
}

// swizzled byte offset within one stage tile: 128 rows x 64B (4 chunks of 16B)
__device__ __forceinline__ uint32_t swz(int row, int chunk) {
    return (uint32_t)(row * 64 + ((chunk ^ ((row >> 1) & 3)) << 4));
}

// =====================================================================
//  fp16 mma.sync GEMM: C[M, CS-cols] = A[M,512] @ Bt[N,512]^T + epilogue
//  tile 128x128, 8 warps (4M x 2N), kblock 32, 4-stage cp.async.
//  Bias selected per 512-col segment (QKV fusion).
//  EPI 0: +bias +pos_emb ; 1: +bias ; 2: leaky(+bias)
//  H16: write __half output (for qkv) instead of float.
// =====================================================================
#define STG 4
#define STAGE_BYTES 8192                 // 128 rows * 64B  (= K-chunk of 32 fp16)
#define SMEM_GEMM (2 * STG * STAGE_BYTES) // 64KB
#define KBLKS 16                          // 512 / 32

template<int EPI, bool H16>
__global__ void __launch_bounds__(256, 2)
mmagemm16(const __half* __restrict__ A, const __half* __restrict__ Bt,
          const float* __restrict__ b0p, const float* __restrict__ b1p,
          const float* __restrict__ b2p, const float* __restrict__ extra,
          void* __restrict__ Cv, int M, int CS)
{
    extern __shared__ char smem[];
    const uint32_t aBase = smem_u32(smem);
    const uint32_t bBase = aBase + STG * STAGE_BYTES;
    const int tid = threadIdx.x, wid = tid >> 5, lane = tid & 31;
    const int nt = blockIdx.x, mt = blockIdx.y;
    const int warpM = wid & 3, warpN = wid >> 2;

    // loader mapping: thread -> (rows lrow, lrow+64 ; 16B chunk lch)
    const int lrow = tid >> 2, lch = tid & 3;
    const __half* ag0 = A + (size_t)(mt * 128 + lrow) * NH + lch * 8;
    const __half* bg0 = Bt + (size_t)(nt * 128 + lrow) * NH + lch * 8;
    const uint32_t sA0 = swz(lrow, lch), sA1 = swz(lrow + 64, lch);

#define LOAD_STAGE(kb, stg) do { \
    const __half* _ag = ag0 + (kb) * 32; \
    const __half* _bg = bg0 + (kb) * 32; \
    uint32_t _da = aBase + (stg) * STAGE_BYTES; \
    uint32_t _db = bBase + (stg) * STAGE_BYTES; \
    CP_ASYNC16(_da + sA0, _ag); \
    CP_ASYNC16(_da + sA1, _ag + (size_t)64 * NH); \
    CP_ASYNC16(_db + sA0, _bg); \
    CP_ASYNC16(_db + sA1, _bg + (size_t)64 * NH); \
    CP_COMMIT(); \
} while (0)

    LOAD_STAGE(0, 0);
    LOAD_STAGE(1, 1);
    LOAD_STAGE(2, 2);

    const int lr = lane & 7;
    const int aRowB = warpM * 32 + lr + ((lane >> 3) & 1) * 8;   // + mi*16
    const int aChB  = (lane >> 4);                               // + ks*2
    const int bRowB = warpN * 64 + lr + (lane >> 4) * 8;         // + p*16
    const int bChB  = (lane >> 3) & 1;                           // + ks*2

    float acc[64];
#pragma unroll
    for (int i = 0; i < 64; i++) acc[i] = 0.f;

    for (int kb = 0; kb < KBLKS; kb++) {
        const int stg = kb & 3;
        CP_WAIT(2);
        __syncthreads();
        if (kb + 3 < KBLKS) LOAD_STAGE(kb + 3, (kb + 3) & 3);

        const uint32_t da = aBase + stg * STAGE_BYTES;
        const uint32_t db = bBase + stg * STAGE_BYTES;
#pragma unroll
        for (int ks = 0; ks < 2; ks++) {
            uint32_t af[2][4];
#pragma unroll
            for (int mi = 0; mi < 2; mi++)
                ldsm4(af[mi], da + swz(aRowB + mi * 16, ks * 2 + aChB));
#pragma unroll
            for (int p = 0; p < 4; p++) {
                uint32_t bf[4];
                ldsm4(bf, db + swz(bRowB + p * 16, ks * 2 + bChB));
#pragma unroll
                for (int mi = 0; mi < 2; mi++) {
                    mma16816f(&acc[(mi * 8 + 2 * p + 0) * 4], af[mi], bf + 0);
                    mma16816f(&acc[(mi * 8 + 2 * p + 1) * 4], af[mi], bf + 2);
                }
            }
        }
        __syncthreads();
    }

    // epilogue
    float* Cf = (float*)Cv;
    __half* Ch = (__half*)Cv;
#pragma unroll
    for (int mi = 0; mi < 2; mi++) {
#pragma unroll
        for (int ntile = 0; ntile < 8; ntile++) {
            const float* c = &acc[(mi * 8 + ntile) * 4];
            int row0 = mt * 128 + warpM * 32 + mi * 16 + (lane >> 2);
            int col  = nt * 128 + warpN * 64 + ntile * 8 + (lane & 3) * 2;
            int seg = col >> 9;
            const float* bp = (seg == 0) ? b0p : (seg == 1) ? b1p : b2p;
            int cl = col & 511;
            float bb0 = bp[cl], bb1 = bp[cl + 1];
#pragma unroll
            for (int half0 = 0; half0 < 2; half0++) {
                int row = row0 + half0 * 8;
                if (row >= M) continue;
                float ox = c[half0 * 2 + 0] + bb0;
                float oy = c[half0 * 2 + 1] + bb1;
                if (EPI == 0) {
                    const float* e = extra + (size_t)(row & (NL - 1)) * NH + col;
                    ox += e[0]; oy += e[1];
                }
                if (EPI == 2) {
                    ox = ox > 0.f ? ox : 0.2f * ox;
                    oy = oy > 0.f ? oy : 0.2f * oy;
                }
                if (H16) {
                    *(__half2*)(Ch + (size_t)row * CS + col) = __floats2half2_rn(ox, oy);
                } else {
                    *(float2*)(Cf + (size_t)row * CS + col) = make_float2(ox, oy);
                }
            }
        }
    }
#undef LOAD_STAGE
}

// ---------------- A conversion: fp32 -> fp16 (for `data` only) --------------
__global__ __launch_bounds__(256) void convA16_k(const float* __restrict__ in,
                                                 __half* __restrict__ out, int n4)
{
    int i = blockIdx.x * 256 + threadIdx.x;
    if (i >= n4) return;
    float4 x = ((const float4*)in)[i];
    ((__half2*)out)[i * 2]     = __floats2half2_rn(x.x, x.y);
    ((__half2*)out)[i * 2 + 1] = __floats2half2_rn(x.z, x.w);
}

// ---------------- ALL weight transposes -> fp16 in ONE launch ---------------
__global__ __launch_bounds__(256) void convB_all_k(
    const float* __restrict__ fc_w, const float* __restrict__ wq,
    const float* __restrict__ wk,   const float* __restrict__ wv,
    const float* __restrict__ wo,   __half* __restrict__ b16)
{
    __shared__ float t[32][33];
    int s = blockIdx.z;
    const float* W;
    __half* Bt;
    if (s == 0) {
        W = fc_w; Bt = b16;
    } else {
        int i = (s - 1) >> 2, j = (s - 1) & 3;
        const float* src = (j == 0) ? wq : (j == 1) ? wk : (j == 2) ? wv : wo;
        W  = src + (size_t)i * NH * NH;
        Bt = b16 + (size_t)(512 + i * 2048 + j * 512) * NH;
    }
    int k0 = blockIdx.x * 32, n0 = blockIdx.y * 32;
    int tx = threadIdx.x & 31, ty = threadIdx.x >> 5;
#pragma unroll
    for (int i = 0; i < 32; i += 8)
        t[ty + i][tx] = W[(size_t)(k0 + ty + i) * NH + n0 + tx];
    __syncthreads();
#pragma unroll
    for (int i = 0; i < 32; i += 8) {
        int n = n0 + ty + i, k = k0 + tx;
        Bt[(size_t)n * NH + k] = __float2half_rn(t[tx][ty + i]);
    }
}

// ---------------- relay mean, two-phase ----------------
__global__ void relay_part_k(const float* __restrict__ embs, float* __restrict__ part)
{
    int b = blockIdx.y, ch = blockIdx.x, j = threadIdx.x;
    const float* p = embs + ((size_t)b * NL + ch * 64) * NH + j;
    float s = 0.f;
#pragma unroll 8
    for (int l = 0; l < 64; l++) s += p[(size_t)l * NH];
    part[((size_t)b * 32 + ch) * NH + j] = s;
}
__global__ void relay_fin_k(const float* __restrict__ part, float* __restrict__ relay)
{
    int b = blockIdx.x, j = threadIdx.x;
    float s = 0.f;
#pragma unroll
    for (int c = 0; c < 32; c++) s += part[((size_t)b * 32 + c) * NH + j];
    relay[b * NH + j] = s * (1.f / NL);
}

// ---------------- LayerNorm + concat relay -> a16 (fp16) --------------------
__global__ __launch_bounds__(256) void ln_concat_k(
    const float* __restrict__ nodes, const float* __restrict__ relay,
    const float* __restrict__ gamma, const float* __restrict__ beta,
    __half* __restrict__ a16)
{
    __shared__ float2 sh[8];
    int row = blockIdx.x;
    int b = row / NLP1, l = row - b * NLP1;
    int tid = threadIdx.x;
    __half2* dst = (__half2*)(a16 + (size_t)row * NH);

    if (l == NL) {
        float2 x = ((const float2*)(relay + b * NH))[tid];
        dst[tid] = __floats2half2_rn(x.x, x.y);
        return;
    }
    float2 x = ((const float2*)(nodes + ((size_t)b * NL + l) * NH))[tid];
    float2 v = make_float2(x.x + x.y, x.x * x.x + x.y * x.y);
    int lane = tid & 31, w = tid >> 5;
#pragma unroll
    for (int o = 16; o; o >>= 1) {
        v.x += __shfl_xor_sync(0xffffffffu, v.x, o);
        v.y += __shfl_xor_sync(0xffffffffu, v.y, o);
    }
    if (lane == 0) sh[w] = v;
    __syncthreads();
    if (tid == 0) {
        float2 t = sh[0];
#pragma unroll
        for (int i = 1; i < 8; i++) { t.x += sh[i].x; t.y += sh[i].y; }
        sh[0] = t;
    }
    __syncthreads();
    float2 t = sh[0];
    float mu = t.x * (1.f / NH);
    float var = t.y * (1.f / NH) - mu * mu;
    float inv = rsqrtf(var + 1e-6f);
    float2 g = ((const float2*)gamma)[tid];
    float2 bb = ((const float2*)beta)[tid];
    float ox = (x.x - mu) * inv * g.x + bb.x;
    float oy = (x.y - mu) * inv * g.y + bb.y;
    dst[tid] = __floats2half2_rn(ox, oy);
}

// ---------------- ring attention (fp16 qkv) -> a16 (fp16) -------------------
__global__ __launch_bounds__(256) void ring_attn_k(
    const __half* __restrict__ qkv, __half* __restrict__ a16)
{
    int gw = blockIdx.x * 8 + (threadIdx.x >> 5);
    int lane = threadIdx.x & 31;
    int h = gw & 7;
    int l = (gw >> 3) & (NL - 1);
    int b = gw >> 14;
    size_t rb = (size_t)b * NLP1 * QS + (size_t)h * HDIM + lane * 2;
    float2 qv = __half22float2(*(const __half2*)(qkv + rb + (size_t)l * QS));

    const __half* kk = qkv + rb + 512;
    const __half* vv = qkv + rb + 1024;
    float2 z = make_float2(0.f, 0.f);
    float2 km = (l > 0)      ? __half22float2(*(const __half2*)(kk + (size_t)(l - 1) * QS)) : z;
    float2 kc =                __half22float2(*(const __half2*)(kk + (size_t)l       * QS));
    float2 kp = (l < NL - 1) ? __half22float2(*(const __half2*)(kk + (size_t)(l + 1) * QS)) : z;
    float2 kr =                __half22float2(*(const __half2*)(kk + (size_t)NL      * QS));
    float s0 = qv.x * km.x + qv.y * km.y;
    float s1 = qv.x * kc.x + qv.y * kc.y;
    float s2 = qv.x * kp.x + qv.y * kp.y;
    float s3 = qv.x * kr.x + qv.y * kr.y;
#pragma unroll
    for (int o = 16; o; o >>= 1) {
        s0 += __shfl_xor_sync(0xffffffffu, s0, o);
        s1 += __shfl_xor_sync(0xffffffffu, s1, o);
        s2 += __shfl_xor_sync(0xffffffffu, s2, o);
        s3 += __shfl_xor_sync(0xffffffffu, s3, o);
    }
    const float scale = 0.125f;
    s0 *= scale; s1 *= scale; s2 *= scale; s3 *= scale;
    float m = fmaxf(fmaxf(s0, s1), fmaxf(s2, s3));
    float e0 = __expf(s0 - m), e1 = __expf(s1 - m);
    float e2 = __expf(s2 - m), e3 = __expf(s3 - m);
    float inv = 1.f / (e0 + e1 + e2 + e3);
    float2 vm = (l > 0)      ? __half22float2(*(const __half2*)(vv + (size_t)(l - 1) * QS)) : z;
    float2 vc =                __half22float2(*(const __half2*)(vv + (size_t)l       * QS));
    float2 vp = (l < NL - 1) ? __half22float2(*(const __half2*)(vv + (size_t)(l + 1) * QS)) : z;
    float2 vr =                __half22float2(*(const __half2*)(vv + (size_t)NL      * QS));
    float ox = (e0 * vm.x + e1 * vc.x + e2 * vp.x + e3 * vr.x) * inv;
    float oy = (e0 * vm.y + e1 * vc.y + e2 * vp.y + e3 * vr.y) * inv;

    __half2* dst = (__half2*)(a16 + ((size_t)b * NL + l) * NH + (size_t)h * HDIM);
    dst[lane] = __floats2half2_rn(ox, oy);
}

// ---------------- star attention (fp16 qkv) ----------------
__global__ __launch_bounds__(256) void star_attn_k(
    const __half* __restrict__ qkv, float* __restrict__ attr)
{
    __shared__ float sq[HDIM];
    __shared__ float sc[NLP1];
    __shared__ float red[8];
    __shared__ float part[4][HDIM];
    int b = blockIdx.x >> 3, h = blockIdx.x & 7;
    int tid = threadIdx.x;
    size_t hb = (size_t)b * NLP1 * QS + (size_t)h * HDIM;
    if (tid < HDIM) sq[tid] = __half2float(qkv[hb + (size_t)NL * QS + tid]);  // relay q
    __syncthreads();
    float lmax = -1e30f;
    for (int l = tid; l < NLP1; l += 256) {
        const __half2* kp = (const __half2*)(qkv + hb + 512 + (size_t)l * QS);
        float d = 0.f;
#pragma unroll
        for (int j = 0; j < HDIM / 2; j++) {
            float2 kk = __half22float2(kp[j]);
            d += sq[2 * j] * kk.x + sq[2 * j + 1] * kk.y;
        }
        d *= 0.125f;
        sc[l] = d;
        lmax = fmaxf(lmax, d);
    }
    int lane = tid & 31, w = tid >> 5;
#pragma unroll
    for (int o = 16; o; o >>= 1) lmax = fmaxf(lmax, __shfl_xor_sync(0xffffffffu, lmax, o));
    if (lane == 0) red[w] = lmax;
    __syncthreads();
    if (tid == 0) {
        float m = red[0];
#pragma unroll
        for (int i = 1; i < 8; i++) m = fmaxf(m, red[i]);
        red[0] = m;
    }
    __syncthreads();
    float m = red[0];
    __syncthreads();
    float lsum = 0.f;
    for (int l = tid; l < NLP1; l += 256) {
        float e = __expf(sc[l] - m);
        sc[l] = e;
        lsum += e;
    }
#pragma unroll
    for (int o = 16; o; o >>= 1) lsum += __shfl_xor_sync(0xffffffffu, lsum, o);
    if (lane == 0) red[w] = lsum;
    __syncthreads();
    if (tid == 0) {
        float s = 0.f;
#pragma unroll
        for (int i = 0; i < 8; i++) s += red[i];
        red[0] = s;
    }
    __syncthreads();
    float Zinv = 1.f / red[0];
    int d = tid & 63, g = tid >> 6;
    float acc = 0.f;
    for (int l = g; l < NLP1; l += 4)
        acc += sc[l] * __half2float(qkv[hb + 1024 + (size_t)l * QS + d]);
    part[g][d] = acc;
    __syncthreads();
    if (tid < HDIM)
        attr[(size_t)b * NH + h * HDIM + tid] =
            (part[0][tid] + part[1][tid] + part[2][tid] + part[3][tid]) * Zinv;
}

// ---------------- star output GEMM + leaky (widened: 64 blocks) -------------
__global__ __launch_bounds__(256) void star_out_k(
    const float* __restrict__ attr, const float* __restrict__ w,
    const float* __restrict__ bias, float* __restrict__ relay)
{
    __shared__ float sa[512];
    __shared__ float red[4][64];
    int b = blockIdx.y, cx = blockIdx.x;
    int t = threadIdx.x;
    sa[t]       = attr[b * NH + t];
    sa[t + 256] = attr[b * NH + t + 256];
    __syncthreads();
    int col = cx * 64 + (t & 63), g = t >> 6;
    float acc = 0.f;
    const float* wp = w + (size_t)(g * 128) * NH + col;
#pragma unroll 4
    for (int kk = 0; kk < 128; kk++)
        acc += sa[g * 128 + kk] * wp[(size_t)kk * NH];
    red[g][t & 63] = acc;
    __syncthreads();
    if (t < 64) {
        float a = red[0][t] + red[1][t] + red[2][t] + red[3][t] + bias[cx * 64 + t];
        relay[b * NH + cx * 64 + t] = a > 0.f ? a : 0.2f * a;
    }
}

// ---------------- final max, two-phase ----------------
__global__ void final_part_k(const float* __restrict__ nodes, float* __restrict__ part)
{
    int b = blockIdx.y, ch = blockIdx.x, j = threadIdx.x;
    const float* p = nodes + ((size_t)b * NL + ch * 64) * NH + j;
    float m = -3.4e38f;
#pragma unroll 8
    for (int l = 0; l < 64; l++) m = fmaxf(m, p[(size_t)l * NH]);
    part[((size_t)b * 32 + ch) * NH + j] = m;
}
__global__ void final_fin_k(const float* __restrict__ part,
                            const float* __restrict__ relay, float* __restrict__ out)
{
    int b = blockIdx.x, j = threadIdx.x;
    float m = -3.4e38f;
#pragma unroll
    for (int c = 0; c < 32; c++) m = fmaxf(m, part[((size_t)b * 32 + c) * NH + j]);
    out[b * NH + j] = 0.5f * (relay[b * NH + j] + m);
}

// =====================================================================
//  host launch
// =====================================================================
extern "C" void kernel_launch(void* const* d_in, const int* in_sizes, int n_in,
                              void* d_out, int out_size)
{
    const float* data    = (const float*)d_in[0];
    const float* fc_w    = (const float*)d_in[1];
    const float* fc_b    = (const float*)d_in[2];
    const float* pos_emb = (const float*)d_in[3];
    const float* ln_g    = (const float*)d_in[4];
    const float* ln_b    = (const float*)d_in[5];
    const float* wq      = (const float*)d_in[6];
    const float* wk      = (const float*)d_in[7];
    const float* wv      = (const float*)d_in[8];
    const float* bq      = (const float*)d_in[9];
    const float* bk      = (const float*)d_in[10];
    const float* bv      = (const float*)d_in[11];
    const float* ring_wo = (const float*)d_in[12];
    const float* ring_bo = (const float*)d_in[13];
    const float* star_wo = (const float*)d_in[14];
    const float* star_bo = (const float*)d_in[15];
    float* out = (float*)d_out;

    float *nodes, *relay, *attr, *part;
    __half *a16, *b16, *qkv;
    cudaGetSymbolAddress((void**)&nodes, g_nodes);
    cudaGetSymbolAddress((void**)&qkv,   g_qkv);
    cudaGetSymbolAddress((void**)&relay, g_relay);
    cudaGetSymbolAddress((void**)&attr,  g_attr);
    cudaGetSymbolAddress((void**)&part,  g_part);
    cudaGetSymbolAddress((void**)&a16,   g_a16);
    cudaGetSymbolAddress((void**)&b16,   g_b16);

    // one-time resources (streams/events are not device-memory allocations)
    static bool init_done = false;
    static cudaStream_t s2;
    static cudaEvent_t evFork[NLAYERS], evJoin[NLAYERS], evFork0, evConvB;
    if (!init_done) {
        cudaFuncSetAttribute(mmagemm16<0,false>, cudaFuncAttributeMaxDynamicSharedMemorySize, SMEM_GEMM);
        cudaFuncSetAttribute(mmagemm16<1,true>,  cudaFuncAttributeMaxDynamicSharedMemorySize, SMEM_GEMM);
        cudaFuncSetAttribute(mmagemm16<2,false>, cudaFuncAttributeMaxDynamicSharedMemorySize, SMEM_GEMM);
        cudaStreamCreateWithFlags(&s2, cudaStreamNonBlocking);
        for (int i = 0; i < NLAYERS; i++) {
            cudaEventCreateWithFlags(&evFork[i], cudaEventDisableTiming);
            cudaEventCreateWithFlags(&evJoin[i], cudaEventDisableTiming);
        }
        cudaEventCreateWithFlags(&evFork0, cudaEventDisableTiming);
        cudaEventCreateWithFlags(&evConvB, cudaEventDisableTiming);
        init_done = true;
    }
    cudaStream_t s0 = (cudaStream_t)0;

    const int M_nodes = NB * NL;     // 16384
    const int M_xy    = NB * NLP1;   // 16392
    dim3 gN(4, M_nodes / 128);       // (4,128)  N=512
    dim3 gQKV(12, (M_xy + 127) / 128); // (12,129) N=1536

    // ---- fork s2 from the capture origin stream FIRST (graph-capture rule),
    //      then run weight conversion on s2 concurrent with data conversion on s0
    cudaEventRecord(evFork0, s0);
    cudaStreamWaitEvent(s2, evFork0, 0);
    convB_all_k<<<dim3(16, 16, 1 + NLAYERS * 4), 256, 0, s2>>>(fc_w, wq, wk, wv, ring_wo, b16);
    cudaEventRecord(evConvB, s2);
    convA16_k<<<(M_nodes * 128 + 255) / 256, 256>>>(data, a16, M_nodes * 128);
    cudaStreamWaitEvent(s0, evConvB, 0);

    // ---- embeddings ----
    mmagemm16<0,false><<<gN, 256, SMEM_GEMM>>>(a16, b16, fc_b, fc_b, fc_b, pos_emb,
                                               nodes, M_nodes, NH);
    relay_part_k<<<dim3(32, NB), NH>>>(nodes, part);
    relay_fin_k<<<NB, NH>>>(part, relay);

    for (int i = 0; i < NLAYERS; i++) {
        size_t bOff = (size_t)i * 512;
        __half* slot  = b16 + (size_t)(512 + i * 2048) * NH;
        __half* slotO = slot + (size_t)1536 * NH;

        if (i > 0) cudaStreamWaitEvent(s0, evJoin[i - 1], 0);  // relay ready
        ln_concat_k<<<NB * NLP1, 256>>>(nodes, relay, ln_g + bOff, ln_b + bOff, a16);

        mmagemm16<1,true><<<gQKV, 256, SMEM_GEMM>>>(a16, slot, bq + bOff, bk + bOff,
                                                    bv + bOff, nullptr, qkv, M_xy, QS);

        // fork: star branch on s2 (depends only on qkv), overlaps ring branch
        cudaEventRecord(evFork[i], s0);
        cudaStreamWaitEvent(s2, evFork[i], 0);
        star_attn_k<<<NB * NHEADS, 256, 0, s2>>>(qkv, attr);
        star_out_k<<<dim3(8, NB), 256, 0, s2>>>(attr, star_wo + (size_t)i * 512 * 512,
                                                star_bo + bOff, relay);
        cudaEventRecord(evJoin[i], s2);

        ring_attn_k<<<NB * NL * NHEADS / 8, 256>>>(qkv, a16);
        mmagemm16<2,false><<<gN, 256, SMEM_GEMM>>>(a16, slotO, ring_bo + bOff, ring_bo + bOff,
                                                   ring_bo + bOff, nullptr, nodes, M_nodes, NH);
    }

    final_part_k<<<dim3(32, NB), NH>>>(nodes, part);
    cudaStreamWaitEvent(s0, evJoin[NLAYERS - 1], 0);           // relay ready
    final_fin_k<<<NB, NH>>>(part, relay, out);
}